// round 1
// baseline (speedup 1.0000x reference)
#include <cuda_runtime.h>

#define LEADS 42
#define HID   10
#define BT    32          // batch rows per block tile
#define THREADS 256
#define ROWF  86          // padded floats per b-row in shared (42*2 = 84 -> 86)

__device__ __forceinline__ float tanh_approx(float x) {
    float y;
    asm("tanh.approx.f32 %0, %1;" : "=f"(y) : "f"(x));
    return y;
}

__global__ __launch_bounds__(THREADS)
void perlead_lstm_kernel(const float* __restrict__ x,
                         const float* __restrict__ W_ih,
                         const float* __restrict__ b_ih,
                         const float* __restrict__ b_hh,
                         const float* __restrict__ W_fc,
                         const float* __restrict__ b_fc,
                         float* __restrict__ y)
{
    // Packed weights: per (t,h) 12 floats:
    // [wi0,wi1,bi, wg0,wg1,bg, wo0,wo1,bo, wf0,wf1, pad]
    // (i and o gates pre-scaled by 0.5 for sigmoid-via-tanh)
    __shared__ float4 sw4[LEADS * HID * 3];
    __shared__ float  sbfc[LEADS * 2];
    __shared__ float2 sx2[BT * (ROWF / 2)];   // 32 rows x 43 float2

    float*       swf = reinterpret_cast<float*>(sw4);
    float*       sxf = reinterpret_cast<float*>(sx2);

    const int tid  = threadIdx.x;
    const int lane = tid & 31;
    const int warp = tid >> 5;
    const long base = (long)blockIdx.x * (BT * LEADS * 2);

    // ---- stage x tile (coalesced global read) ----
    for (int idx = tid; idx < BT * LEADS * 2; idx += THREADS) {
        int bl = idx / (LEADS * 2);
        int j  = idx - bl * (LEADS * 2);
        sxf[bl * ROWF + j] = x[base + idx];
    }

    // ---- pack weights into shared ----
    for (int u = tid; u < LEADS * HID; u += THREADS) {
        int t = u / HID;
        int h = u - t * HID;
        const float* Wt = W_ih + (long)t * 40 * 2;
        // gate order i(0), f(1 - unused), g(2), o(3)
        float wi0 = Wt[(0 * HID + h) * 2 + 0];
        float wi1 = Wt[(0 * HID + h) * 2 + 1];
        float wg0 = Wt[(2 * HID + h) * 2 + 0];
        float wg1 = Wt[(2 * HID + h) * 2 + 1];
        float wo0 = Wt[(3 * HID + h) * 2 + 0];
        float wo1 = Wt[(3 * HID + h) * 2 + 1];
        float bi  = b_ih[t * 40 + 0 * HID + h] + b_hh[t * 40 + 0 * HID + h];
        float bg  = b_ih[t * 40 + 2 * HID + h] + b_hh[t * 40 + 2 * HID + h];
        float bo  = b_ih[t * 40 + 3 * HID + h] + b_hh[t * 40 + 3 * HID + h];
        float* d = swf + u * 12;
        d[0]  = 0.5f * wi0;  d[1]  = 0.5f * wi1;  d[2]  = 0.5f * bi;
        d[3]  = wg0;         d[4]  = wg1;         d[5]  = bg;
        d[6]  = 0.5f * wo0;  d[7]  = 0.5f * wo1;  d[8]  = 0.5f * bo;
        d[9]  = W_fc[((long)t * 2 + 0) * HID + h];
        d[10] = W_fc[((long)t * 2 + 1) * HID + h];
        d[11] = 0.0f;
    }
    if (tid < LEADS * 2) sbfc[tid] = b_fc[tid];

    __syncthreads();

    // ---- compute: warp-uniform t, lane = local batch row ----
    for (int t = warp; t < LEADS; t += (THREADS / 32)) {
        float2 xv = sx2[lane * (ROWF / 2) + t];
        float y0 = sbfc[t * 2 + 0];
        float y1 = sbfc[t * 2 + 1];
        const float4* wt = sw4 + t * HID * 3;
        #pragma unroll
        for (int h = 0; h < HID; h++) {
            float4 a = wt[h * 3 + 0];
            float4 b = wt[h * 3 + 1];
            float4 c = wt[h * 3 + 2];
            float iv = fmaf(a.x, xv.x, fmaf(a.y, xv.y, a.z));   // 0.5*i
            float gv = fmaf(a.w, xv.x, fmaf(b.x, xv.y, b.y));   // g
            float ov = fmaf(b.z, xv.x, fmaf(b.w, xv.y, c.x));   // 0.5*o
            float si = fmaf(0.5f, tanh_approx(iv), 0.5f);       // sigmoid(i)
            float tg = tanh_approx(gv);                         // tanh(g)
            float so = fmaf(0.5f, tanh_approx(ov), 0.5f);       // sigmoid(o)
            float cv = si * tg;                                 // cell (f*c0 = 0)
            float hh = so * tanh_approx(cv);                    // hidden
            y0 = fmaf(c.y, hh, y0);
            y1 = fmaf(c.z, hh, y1);
        }
        sx2[lane * (ROWF / 2) + t] = make_float2(y0, y1);       // overwrite in place
    }

    __syncthreads();

    // ---- write y tile (coalesced global write) ----
    for (int idx = tid; idx < BT * LEADS * 2; idx += THREADS) {
        int bl = idx / (LEADS * 2);
        int j  = idx - bl * (LEADS * 2);
        y[base + idx] = sxf[bl * ROWF + j];
    }
}

extern "C" void kernel_launch(void* const* d_in, const int* in_sizes, int n_in,
                              void* d_out, int out_size) {
    const float* x    = (const float*)d_in[0];
    const float* W_ih = (const float*)d_in[1];
    const float* b_ih = (const float*)d_in[2];
    const float* b_hh = (const float*)d_in[3];
    const float* W_fc = (const float*)d_in[4];
    const float* b_fc = (const float*)d_in[5];
    float* y = (float*)d_out;

    int B = in_sizes[0] / (LEADS * 2);   // 131072
    int blocks = B / BT;                 // 4096
    perlead_lstm_kernel<<<blocks, THREADS>>>(x, W_ih, b_ih, b_hh, W_fc, b_fc, y);
}

// round 2
// speedup vs baseline: 1.0915x; 1.0915x over previous
#include <cuda_runtime.h>

#define LEADS 42
#define HID   10
#define BT    128         // batch rows per block tile
#define RG    4           // row groups of 32 (BT/32)
#define THREADS 256
#define NWARP (THREADS/32)
#define ROW2  43          // padded float2 per b-row in shared (42 -> 43)

__device__ __forceinline__ float tanh_approx(float x) {
    float y;
    asm("tanh.approx.f32 %0, %1;" : "=f"(y) : "f"(x));
    return y;
}

extern __shared__ float smem_dyn[];

__global__ __launch_bounds__(THREADS)
void perlead_lstm_kernel(const float* __restrict__ x,
                         const float* __restrict__ W_ih,
                         const float* __restrict__ b_ih,
                         const float* __restrict__ b_hh,
                         const float* __restrict__ W_fc,
                         const float* __restrict__ b_fc,
                         float* __restrict__ y)
{
    // layout in dynamic smem:
    //   sx2  : BT * ROW2 float2          (x tile, overwritten with y in place)
    //   sw4  : LEADS*HID*3 float4        (packed weights)
    //   sbfc : LEADS float2              (fc bias)
    float2* sx2  = reinterpret_cast<float2*>(smem_dyn);
    float4* sw4  = reinterpret_cast<float4*>(smem_dyn + BT * ROW2 * 2);
    float2* sbfc = reinterpret_cast<float2*>(smem_dyn + BT * ROW2 * 2 + LEADS * HID * 12);
    float*  swf  = reinterpret_cast<float*>(sw4);

    const int tid  = threadIdx.x;
    const int lane = tid & 31;
    const int warp = tid >> 5;
    const long base2 = (long)blockIdx.x * (BT * LEADS);   // in float2 units

    // ---- stage x tile (coalesced float2 global read) ----
    const float2* xg = reinterpret_cast<const float2*>(x) + base2;
    #pragma unroll 1
    for (int idx = tid; idx < BT * LEADS; idx += THREADS) {
        int bl = idx / LEADS;
        int j  = idx - bl * LEADS;
        sx2[bl * ROW2 + j] = xg[idx];
    }

    // ---- pack weights into shared ----
    // per (t,h) 12 floats: [.5wi0,.5wi1,.5bi, wg0,wg1,bg, .5wo0,.5wo1,.5bo, wf0,wf1, pad]
    for (int u = tid; u < LEADS * HID; u += THREADS) {
        int t = u / HID;
        int h = u - t * HID;
        const float* Wt = W_ih + (long)t * 40 * 2;
        float wi0 = Wt[(0 * HID + h) * 2 + 0];
        float wi1 = Wt[(0 * HID + h) * 2 + 1];
        float wg0 = Wt[(2 * HID + h) * 2 + 0];
        float wg1 = Wt[(2 * HID + h) * 2 + 1];
        float wo0 = Wt[(3 * HID + h) * 2 + 0];
        float wo1 = Wt[(3 * HID + h) * 2 + 1];
        float bi  = b_ih[t * 40 + 0 * HID + h] + b_hh[t * 40 + 0 * HID + h];
        float bg  = b_ih[t * 40 + 2 * HID + h] + b_hh[t * 40 + 2 * HID + h];
        float bo  = b_ih[t * 40 + 3 * HID + h] + b_hh[t * 40 + 3 * HID + h];
        float* d = swf + u * 12;
        d[0]  = 0.5f * wi0;  d[1]  = 0.5f * wi1;  d[2]  = 0.5f * bi;
        d[3]  = wg0;         d[4]  = wg1;         d[5]  = bg;
        d[6]  = 0.5f * wo0;  d[7]  = 0.5f * wo1;  d[8]  = 0.5f * bo;
        d[9]  = W_fc[((long)t * 2 + 0) * HID + h];
        d[10] = W_fc[((long)t * 2 + 1) * HID + h];
        d[11] = 0.0f;
    }
    if (tid < LEADS) {
        sbfc[tid] = make_float2(b_fc[tid * 2 + 0], b_fc[tid * 2 + 1]);
    }

    __syncthreads();

    // ---- compute: warp-uniform t; each weight load serves RG*32 rows ----
    for (int t = warp; t < LEADS; t += NWARP) {
        float2 xv[RG];
        float  y0[RG], y1[RG];
        float2 bfc = sbfc[t];
        #pragma unroll
        for (int r = 0; r < RG; r++) {
            xv[r] = sx2[(r * 32 + lane) * ROW2 + t];
            y0[r] = bfc.x;
            y1[r] = bfc.y;
        }
        const float4* wt = sw4 + t * HID * 3;
        #pragma unroll
        for (int h = 0; h < HID; h++) {
            float4 a = wt[h * 3 + 0];
            float4 b = wt[h * 3 + 1];
            float4 c = wt[h * 3 + 2];
            #pragma unroll
            for (int r = 0; r < RG; r++) {
                float iv = fmaf(a.x, xv[r].x, fmaf(a.y, xv[r].y, a.z));  // 0.5*i
                float gv = fmaf(a.w, xv[r].x, fmaf(b.x, xv[r].y, b.y));  // g
                float ov = fmaf(b.z, xv[r].x, fmaf(b.w, xv[r].y, c.x));  // 0.5*o
                float si = fmaf(0.5f, tanh_approx(iv), 0.5f);            // sigmoid(i)
                float tg = tanh_approx(gv);                              // tanh(g)
                float so = fmaf(0.5f, tanh_approx(ov), 0.5f);            // sigmoid(o)
                float cv = si * tg;                                      // cell (f*c0=0)
                float hh = so * tanh_approx(cv);                         // hidden
                y0[r] = fmaf(c.y, hh, y0[r]);
                y1[r] = fmaf(c.z, hh, y1[r]);
            }
        }
        #pragma unroll
        for (int r = 0; r < RG; r++) {
            sx2[(r * 32 + lane) * ROW2 + t] = make_float2(y0[r], y1[r]);
        }
    }

    __syncthreads();

    // ---- write y tile (coalesced float2 global write) ----
    float2* yg = reinterpret_cast<float2*>(y) + base2;
    #pragma unroll 1
    for (int idx = tid; idx < BT * LEADS; idx += THREADS) {
        int bl = idx / LEADS;
        int j  = idx - bl * LEADS;
        yg[idx] = sx2[bl * ROW2 + j];
    }
}

extern "C" void kernel_launch(void* const* d_in, const int* in_sizes, int n_in,
                              void* d_out, int out_size) {
    const float* x    = (const float*)d_in[0];
    const float* W_ih = (const float*)d_in[1];
    const float* b_ih = (const float*)d_in[2];
    const float* b_hh = (const float*)d_in[3];
    const float* W_fc = (const float*)d_in[4];
    const float* b_fc = (const float*)d_in[5];
    float* y = (float*)d_out;

    const int smem_bytes = BT * ROW2 * 8 + LEADS * HID * 48 + LEADS * 8;
    static bool attr_set = false;
    if (!attr_set) {
        cudaFuncSetAttribute(perlead_lstm_kernel,
                             cudaFuncAttributeMaxDynamicSharedMemorySize, smem_bytes);
        attr_set = true;
    }

    int B = in_sizes[0] / (LEADS * 2);   // 131072
    int blocks = B / BT;                 // 1024
    perlead_lstm_kernel<<<blocks, THREADS, smem_bytes>>>(x, W_ih, b_ih, b_hh, W_fc, b_fc, y);
}

// round 4
// speedup vs baseline: 1.1708x; 1.0727x over previous
#include <cuda_runtime.h>

#define LEADS 42
#define HID   10
#define BT    64          // batch rows per block tile
#define RG    2           // row groups of 32 (BT/32)
#define THREADS 256
#define NWARP (THREADS/32)
#define ROW2  43          // padded float2 per b-row in shared (42 -> 43)

// odd-poly fit of tanh(c)/c in u=c^2 on [0,1]: max abs err ~5e-5
#define TC1 (-0.33329204f)
#define TC2 ( 0.13239708f)
#define TC3 (-0.04872334f)
#define TC4 ( 0.0112125f)

__device__ __forceinline__ float tanh_approx(float x) {
    float y;
    asm("tanh.approx.f32 %0, %1;" : "=f"(y) : "f"(x));
    return y;
}

extern __shared__ float smem_dyn[];

__global__ __launch_bounds__(THREADS)
void perlead_lstm_kernel(const float* __restrict__ x,
                         const float* __restrict__ W_ih,
                         const float* __restrict__ b_ih,
                         const float* __restrict__ b_hh,
                         const float* __restrict__ W_fc,
                         const float* __restrict__ b_fc,
                         float* __restrict__ y)
{
    // dynamic smem layout:
    //   sx2  : BT * ROW2 float2          (x tile, overwritten with y in place)
    //   sw4  : LEADS*HID*3 float4        (packed weights)
    //   sbfc : LEADS float2              (fc bias)
    float2* sx2  = reinterpret_cast<float2*>(smem_dyn);
    float4* sw4  = reinterpret_cast<float4*>(smem_dyn + BT * ROW2 * 2);
    float2* sbfc = reinterpret_cast<float2*>(smem_dyn + BT * ROW2 * 2 + LEADS * HID * 12);
    float*  swf  = reinterpret_cast<float*>(sw4);

    const int tid  = threadIdx.x;
    const int lane = tid & 31;
    const int warp = tid >> 5;
    const long base2 = (long)blockIdx.x * (BT * LEADS);   // float2 units

    // ---- stage x tile (coalesced float2 global read) ----
    const float2* xg = reinterpret_cast<const float2*>(x) + base2;
    #pragma unroll 1
    for (int idx = tid; idx < BT * LEADS; idx += THREADS) {
        int bl = idx / LEADS;
        int j  = idx - bl * LEADS;
        sx2[bl * ROW2 + j] = xg[idx];
    }

    // ---- pack weights into shared ----
    // per (t,h) 12 floats: [.5wi0,.5wi1,.5bi, wg0,wg1,bg, .5wo0,.5wo1,.5bo, wf0,wf1, pad]
    for (int u = tid; u < LEADS * HID; u += THREADS) {
        int t = u / HID;
        int h = u - t * HID;
        const float* Wt = W_ih + (long)t * 40 * 2;
        float wi0 = Wt[(0 * HID + h) * 2 + 0];
        float wi1 = Wt[(0 * HID + h) * 2 + 1];
        float wg0 = Wt[(2 * HID + h) * 2 + 0];
        float wg1 = Wt[(2 * HID + h) * 2 + 1];
        float wo0 = Wt[(3 * HID + h) * 2 + 0];
        float wo1 = Wt[(3 * HID + h) * 2 + 1];
        float bi  = b_ih[t * 40 + 0 * HID + h] + b_hh[t * 40 + 0 * HID + h];
        float bg  = b_ih[t * 40 + 2 * HID + h] + b_hh[t * 40 + 2 * HID + h];
        float bo  = b_ih[t * 40 + 3 * HID + h] + b_hh[t * 40 + 3 * HID + h];
        float* d = swf + u * 12;
        d[0]  = 0.5f * wi0;  d[1]  = 0.5f * wi1;  d[2]  = 0.5f * bi;
        d[3]  = wg0;         d[4]  = wg1;         d[5]  = bg;
        d[6]  = 0.5f * wo0;  d[7]  = 0.5f * wo1;  d[8]  = 0.5f * bo;
        d[9]  = W_fc[((long)t * 2 + 0) * HID + h];
        d[10] = W_fc[((long)t * 2 + 1) * HID + h];
        d[11] = 0.0f;
    }
    if (tid < LEADS) {
        sbfc[tid] = make_float2(b_fc[tid * 2 + 0], b_fc[tid * 2 + 1]);
    }

    __syncthreads();

    // ---- compute: warp-uniform t; each weight load serves RG*32 rows ----
    for (int t = warp; t < LEADS; t += NWARP) {
        float2 xv[RG];
        float  y0[RG], y1[RG];
        float2 bfc = sbfc[t];
        #pragma unroll
        for (int r = 0; r < RG; r++) {
            xv[r] = sx2[(r * 32 + lane) * ROW2 + t];
            y0[r] = bfc.x;
            y1[r] = bfc.y;
        }
        const float4* wt = sw4 + t * HID * 3;
        #pragma unroll
        for (int h = 0; h < HID; h++) {
            float4 a = wt[h * 3 + 0];
            float4 b = wt[h * 3 + 1];
            float4 c = wt[h * 3 + 2];
            #pragma unroll
            for (int r = 0; r < RG; r++) {
                float iv = fmaf(a.x, xv[r].x, fmaf(a.y, xv[r].y, a.z));  // 0.5*i
                float gv = fmaf(a.w, xv[r].x, fmaf(b.x, xv[r].y, b.y));  // g
                float ov = fmaf(b.z, xv[r].x, fmaf(b.w, xv[r].y, c.x));  // 0.5*o
                float si = fmaf(0.5f, tanh_approx(iv), 0.5f);            // sigmoid(i)
                float tg = tanh_approx(gv);                              // tanh(g)
                float so = fmaf(0.5f, tanh_approx(ov), 0.5f);            // sigmoid(o)
                float cv = si * tg;                                      // cell, |cv|<1
                // tanh(cv) via odd poly (FMA pipe, no MUFU)
                float u2 = cv * cv;
                float q  = fmaf(fmaf(fmaf(TC4, u2, TC3), u2, TC2), u2, TC1);
                float p  = fmaf(u2, q, 1.0f);                            // tanh(cv)/cv
                float hh = (so * cv) * p;                                // sigmoid(o)*tanh(cv)
                y0[r] = fmaf(c.y, hh, y0[r]);
                y1[r] = fmaf(c.z, hh, y1[r]);
            }
        }
        #pragma unroll
        for (int r = 0; r < RG; r++) {
            sx2[(r * 32 + lane) * ROW2 + t] = make_float2(y0[r], y1[r]);
        }
    }

    __syncthreads();

    // ---- write y tile (coalesced float2 global write) ----
    float2* yg = reinterpret_cast<float2*>(y) + base2;
    #pragma unroll 1
    for (int idx = tid; idx < BT * LEADS; idx += THREADS) {
        int bl = idx / LEADS;
        int j  = idx - bl * LEADS;
        yg[idx] = sx2[bl * ROW2 + j];
    }
}

extern "C" void kernel_launch(void* const* d_in, const int* in_sizes, int n_in,
                              void* d_out, int out_size) {
    const float* x    = (const float*)d_in[0];
    const float* W_ih = (const float*)d_in[1];
    const float* b_ih = (const float*)d_in[2];
    const float* b_hh = (const float*)d_in[3];
    const float* W_fc = (const float*)d_in[4];
    const float* b_fc = (const float*)d_in[5];
    float* y = (float*)d_out;

    const int smem_bytes = BT * ROW2 * 8 + LEADS * HID * 48 + LEADS * 8;
    static bool attr_set = false;
    if (!attr_set) {
        cudaFuncSetAttribute(perlead_lstm_kernel,
                             cudaFuncAttributeMaxDynamicSharedMemorySize, smem_bytes);
        attr_set = true;
    }

    int B = in_sizes[0] / (LEADS * 2);   // 131072
    int blocks = B / BT;                 // 2048
    perlead_lstm_kernel<<<blocks, THREADS, smem_bytes>>>(x, W_ih, b_ih, b_hh, W_fc, b_fc, y);
}

// round 7
// speedup vs baseline: 1.2229x; 1.0445x over previous
#include <cuda_runtime.h>

#define LEADS 42
#define HID   10
#define BT    64          // batch rows per block tile
#define RG    2           // row groups of 32 (BT/32)
#define THREADS 256
#define NWARP (THREADS/32)
#define ROW2  43          // padded float2 per b-row in shared (42 -> 43)

// tanh(m/2) = 0.5*m*Q(m^2), Q(v) = 1 + QC1*v + QC2*v^2 + QC3*v^3 + QC4*v^4
// (rescaled from tanh(c)/c fit on |c|<=1, max abs err ~5e-5)
#define QC1 (-0.08332301f)
#define QC2 ( 0.0082748175f)
#define QC3 (-0.000761302f)
#define QC4 ( 4.3798828e-5f)

__device__ __forceinline__ float tanh_approx(float x) {
    float y;
    asm("tanh.approx.f32 %0, %1;" : "=f"(y) : "f"(x));
    return y;
}

extern __shared__ float smem_dyn[];

__global__ __launch_bounds__(THREADS)
void perlead_lstm_kernel(const float* __restrict__ x,
                         const float* __restrict__ W_ih,
                         const float* __restrict__ b_ih,
                         const float* __restrict__ b_hh,
                         const float* __restrict__ W_fc,
                         const float* __restrict__ b_fc,
                         float* __restrict__ y)
{
    // dynamic smem layout:
    //   sx2  : BT * ROW2 float2          (x tile, overwritten with y in place)
    //   sw4  : LEADS*HID*3 float4        (packed weights)
    //   sbfc : LEADS float2              (fc bias)
    float2* sx2  = reinterpret_cast<float2*>(smem_dyn);
    float4* sw4  = reinterpret_cast<float4*>(smem_dyn + BT * ROW2 * 2);
    float2* sbfc = reinterpret_cast<float2*>(smem_dyn + BT * ROW2 * 2 + LEADS * HID * 12);
    float*  swf  = reinterpret_cast<float*>(sw4);

    const int tid  = threadIdx.x;
    const int lane = tid & 31;
    const int warp = tid >> 5;
    const long base2 = (long)blockIdx.x * (BT * LEADS);   // float2 units

    // ---- stage x tile (coalesced float2 global read) ----
    const float2* xg = reinterpret_cast<const float2*>(x) + base2;
    #pragma unroll 1
    for (int idx = tid; idx < BT * LEADS; idx += THREADS) {
        int bl = idx / LEADS;
        int j  = idx - bl * LEADS;
        sx2[bl * ROW2 + j] = xg[idx];
    }

    // ---- pack weights into shared ----
    // per (t,h) 12 floats:
    // [.5wi0,.5wi1,.5bi, wg0,wg1,bg, .5wo0,.5wo1,.5bo, .25wf0,.25wf1, pad]
    for (int u = tid; u < LEADS * HID; u += THREADS) {
        int t = u / HID;
        int h = u - t * HID;
        const float* Wt = W_ih + (long)t * 40 * 2;
        float wi0 = Wt[(0 * HID + h) * 2 + 0];
        float wi1 = Wt[(0 * HID + h) * 2 + 1];
        float wg0 = Wt[(2 * HID + h) * 2 + 0];
        float wg1 = Wt[(2 * HID + h) * 2 + 1];
        float wo0 = Wt[(3 * HID + h) * 2 + 0];
        float wo1 = Wt[(3 * HID + h) * 2 + 1];
        float bi  = b_ih[t * 40 + 0 * HID + h] + b_hh[t * 40 + 0 * HID + h];
        float bg  = b_ih[t * 40 + 2 * HID + h] + b_hh[t * 40 + 2 * HID + h];
        float bo  = b_ih[t * 40 + 3 * HID + h] + b_hh[t * 40 + 3 * HID + h];
        float* d = swf + u * 12;
        d[0]  = 0.5f * wi0;   d[1]  = 0.5f * wi1;   d[2]  = 0.5f * bi;
        d[3]  = wg0;          d[4]  = wg1;          d[5]  = bg;
        d[6]  = 0.5f * wo0;   d[7]  = 0.5f * wo1;   d[8]  = 0.5f * bo;
        d[9]  = 0.25f * W_fc[((long)t * 2 + 0) * HID + h];
        d[10] = 0.25f * W_fc[((long)t * 2 + 1) * HID + h];
        d[11] = 0.0f;
    }
    if (tid < LEADS) {
        sbfc[tid] = make_float2(b_fc[tid * 2 + 0], b_fc[tid * 2 + 1]);
    }

    __syncthreads();

    // ---- compute: warp-uniform t; each weight load serves RG*32 rows ----
    for (int t = warp; t < LEADS; t += NWARP) {
        float2 xv[RG];
        float  y0[RG], y1[RG];
        float2 bfc = sbfc[t];
        #pragma unroll
        for (int r = 0; r < RG; r++) {
            xv[r] = sx2[(r * 32 + lane) * ROW2 + t];
            y0[r] = bfc.x;
            y1[r] = bfc.y;
        }
        const float4* wt = sw4 + t * HID * 3;
        #pragma unroll
        for (int h = 0; h < HID; h++) {
            float4 a = wt[h * 3 + 0];
            float4 b = wt[h * 3 + 1];
            float4 c = wt[h * 3 + 2];
            #pragma unroll
            for (int r = 0; r < RG; r++) {
                float iv = fmaf(a.x, xv[r].x, fmaf(a.y, xv[r].y, a.z));  // i/2
                float gv = fmaf(a.w, xv[r].x, fmaf(b.x, xv[r].y, b.y));  // g
                float ov = fmaf(b.z, xv[r].x, fmaf(b.w, xv[r].y, c.x));  // o/2
                float Ti = tanh_approx(iv);                               // tanh(i/2)
                float Tg = tanh_approx(gv);                               // tanh(g)
                float To = tanh_approx(ov);                               // tanh(o/2)
                float m  = fmaf(Ti, Tg, Tg);                              // 2c = (Ti+1)*Tg
                float v  = m * m;
                float q  = fmaf(fmaf(fmaf(QC4, v, QC3), v, QC2), v, QC1);
                float Qv = fmaf(v, q, 1.0f);
                float s  = m * Qv;                                        // 2*tanh(c)
                float t2 = fmaf(To, s, s);                                // 4*h
                y0[r] = fmaf(c.y, t2, y0[r]);                             // wf' = wf/4
                y1[r] = fmaf(c.z, t2, y1[r]);
            }
        }
        #pragma unroll
        for (int r = 0; r < RG; r++) {
            sx2[(r * 32 + lane) * ROW2 + t] = make_float2(y0[r], y1[r]);
        }
    }

    __syncthreads();

    // ---- write y tile (coalesced float2 global write) ----
    float2* yg = reinterpret_cast<float2*>(y) + base2;
    #pragma unroll 1
    for (int idx = tid; idx < BT * LEADS; idx += THREADS) {
        int bl = idx / LEADS;
        int j  = idx - bl * LEADS;
        yg[idx] = sx2[bl * ROW2 + j];
    }
}

extern "C" void kernel_launch(void* const* d_in, const int* in_sizes, int n_in,
                              void* d_out, int out_size) {
    const float* x    = (const float*)d_in[0];
    const float* W_ih = (const float*)d_in[1];
    const float* b_ih = (const float*)d_in[2];
    const float* b_hh = (const float*)d_in[3];
    const float* W_fc = (const float*)d_in[4];
    const float* b_fc = (const float*)d_in[5];
    float* y = (float*)d_out;

    const int smem_bytes = BT * ROW2 * 8 + LEADS * HID * 48 + LEADS * 8;
    static bool attr_set = false;
    if (!attr_set) {
        cudaFuncSetAttribute(perlead_lstm_kernel,
                             cudaFuncAttributeMaxDynamicSharedMemorySize, smem_bytes);
        attr_set = true;
    }

    int B = in_sizes[0] / (LEADS * 2);   // 131072
    int blocks = B / BT;                 // 2048
    perlead_lstm_kernel<<<blocks, THREADS, smem_bytes>>>(x, W_ih, b_ih, b_hh, W_fc, b_fc, y);
}